// round 4
// baseline (speedup 1.0000x reference)
#include <cuda_runtime.h>
#include <cstdint>

// Problem constants
#define Bq  4
#define Sq  4096
#define DMq 512
#define DOq 64

typedef unsigned long long ull;

// Scratch for projected q, k, v: 3 * 4*4096*64 floats = 12 MB (static device array,
// the allowed scratch mechanism).
static __device__ float g_scratch[3ull * Bq * Sq * DOq];

// ---------------------------------------------------------------------------
// Packed f32x2 helpers (Blackwell sm_100+ packed fp32 pipe)
// ---------------------------------------------------------------------------
__device__ __forceinline__ ull dup2(float v) {
    ull r; unsigned u = __float_as_uint(v);
    asm("mov.b64 %0, {%1, %1};" : "=l"(r) : "r"(u));
    return r;
}
__device__ __forceinline__ ull pack2(float lo, float hi) {
    ull r;
    asm("mov.b64 %0, {%1, %2};"
        : "=l"(r) : "r"(__float_as_uint(lo)), "r"(__float_as_uint(hi)));
    return r;
}
__device__ __forceinline__ float2 unpack2(ull v) {
    return make_float2(__uint_as_float((unsigned)v),
                       __uint_as_float((unsigned)(v >> 32)));
}
__device__ __forceinline__ ull fma2(ull a, ull b, ull c) {
    ull d;
    asm("fma.rn.f32x2 %0, %1, %2, %3;" : "=l"(d) : "l"(a), "l"(b), "l"(c));
    return d;
}
__device__ __forceinline__ ull mul2(ull a, ull b) {
    ull d;
    asm("mul.rn.f32x2 %0, %1, %2;" : "=l"(d) : "l"(a), "l"(b));
    return d;
}

// ---------------------------------------------------------------------------
// Projection: out[row, e] = X[row, :] @ W[:, e] + bias[e]
// X: [16384, 512], W: [512, 64]. One CTA = 64 rows x 64 cols, 256 threads,
// each thread 4x4 outputs packed over row pairs (2 x 4 f32x2 accumulators).
// ---------------------------------------------------------------------------
__global__ __launch_bounds__(256) void proj_kernel(
    const float* __restrict__ X, const float* __restrict__ W,
    const float* __restrict__ bias, int which)
{
    __shared__ float Xts[32][68];   // X chunk transposed: Xts[kk][row]
    __shared__ float Ws[32][64];    // W chunk natural:    Ws[kk][col]

    float* outp = g_scratch + (size_t)which * ((size_t)Bq * Sq * DOq);
    const int tid = threadIdx.x;
    const int ty = tid >> 4, tx = tid & 15;
    const int row0 = blockIdx.x * 64;

    ull acc[2][4];
#pragma unroll
    for (int i = 0; i < 2; i++)
#pragma unroll
        for (int j = 0; j < 4; j++) acc[i][j] = 0ull;

    for (int k0 = 0; k0 < DMq; k0 += 32) {
        __syncthreads();
        // Load X tile transposed (coalesced gmem, 4-way STS conflict - amortized)
#pragma unroll
        for (int i = 0; i < 8; i++) {
            int e = i * 256 + tid;
            int r = e >> 5, kk = e & 31;
            Xts[kk][r] = X[(size_t)(row0 + r) * DMq + (k0 + kk)];
        }
        // Load W tile natural (fully coalesced)
#pragma unroll
        for (int i = 0; i < 8; i++) {
            int e = i * 256 + tid;
            int r = e >> 6, c = e & 63;
            Ws[r][c] = W[(size_t)(k0 + r) * DOq + c];
        }
        __syncthreads();

#pragma unroll
        for (int kk = 0; kk < 32; kk++) {
            // rows (4ty..4ty+3) as two packed pairs, directly from SMEM
            ulonglong2 a = *(const ulonglong2*)&Xts[kk][4 * ty];
            float4 w = *(const float4*)&Ws[kk][4 * tx];
            ull w0 = dup2(w.x), w1 = dup2(w.y), w2 = dup2(w.z), w3 = dup2(w.w);
            acc[0][0] = fma2(a.x, w0, acc[0][0]);
            acc[0][1] = fma2(a.x, w1, acc[0][1]);
            acc[0][2] = fma2(a.x, w2, acc[0][2]);
            acc[0][3] = fma2(a.x, w3, acc[0][3]);
            acc[1][0] = fma2(a.y, w0, acc[1][0]);
            acc[1][1] = fma2(a.y, w1, acc[1][1]);
            acc[1][2] = fma2(a.y, w2, acc[1][2]);
            acc[1][3] = fma2(a.y, w3, acc[1][3]);
        }
    }

    float4 bb = *(const float4*)&bias[4 * tx];
    float bcol[4] = {bb.x, bb.y, bb.z, bb.w};
#pragma unroll
    for (int rr = 0; rr < 2; rr++) {
        float o0[4], o1[4];
#pragma unroll
        for (int c = 0; c < 4; c++) {
            float2 v = unpack2(acc[rr][c]);
            o0[c] = v.x + bcol[c];
            o1[c] = v.y + bcol[c];
        }
        size_t r0 = (size_t)(row0 + 4 * ty + 2 * rr) * DOq + 4 * tx;
        *(float4*)&outp[r0]        = make_float4(o0[0], o0[1], o0[2], o0[3]);
        *(float4*)&outp[r0 + DOq]  = make_float4(o1[0], o1[1], o1[2], o1[3]);
    }
}

// ---------------------------------------------------------------------------
// Flash attention (fp32, online softmax).
// Grid: (S/64, B). Block: 256 threads as 16(ty) x 16(tx).
// Per CTA: Q block of 64 rows x 64 dims. Loop over 128 key tiles of BN=32.
// Thread owns score rows 4ty..4ty+3 / cols 2tx..2tx+1 and output rows
// 4ty..4ty+3 / cols 4tx..4tx+3. Accumulators packed over row pairs (f32x2).
// ---------------------------------------------------------------------------
__global__ __launch_bounds__(256) void attn_kernel(const int* __restrict__ mask,
                                                   float* __restrict__ out)
{
    __shared__ float Qts[64][68];   // Q transposed: Qts[d][qrow]   (16B-aligned pairs)
    __shared__ float Kts[64][33];   // K tile transposed: Kts[d][kcol] (conflict-free stores)
    __shared__ float Vs[32][64];    // V tile natural:    Vs[k][e]
    __shared__ float Pts[32][68];   // P transposed:      Pts[k][qrow]

    const float* gq = g_scratch;
    const float* gk = g_scratch + (size_t)Bq * Sq * DOq;
    const float* gv = g_scratch + 2 * (size_t)Bq * Sq * DOq;

    const int tid = threadIdx.x;
    const int ty = tid >> 4, tx = tid & 15;
    const int q0 = blockIdx.x * 64;
    const int b  = blockIdx.y;
    const float NEGINF = __int_as_float(0xff800000);

    // Load Q block transposed (once)
#pragma unroll
    for (int i = 0; i < 16; i++) {
        int e = i * 256 + tid;
        int r = e >> 6, d = e & 63;
        Qts[d][r] = gq[((size_t)b * Sq + q0 + r) * DOq + d];
    }

    ull O2[2][4];
#pragma unroll
    for (int i = 0; i < 2; i++)
#pragma unroll
        for (int j = 0; j < 4; j++) O2[i][j] = 0ull;

    float m_i[4], l_i[4];
#pragma unroll
    for (int r = 0; r < 4; r++) { m_i[r] = NEGINF; l_i[r] = 0.0f; }

    const int* mrow[4];
#pragma unroll
    for (int r = 0; r < 4; r++)
        mrow[r] = mask + ((size_t)b * Sq + q0 + 4 * ty + r) * Sq + 2 * tx;

    for (int kt = 0; kt < Sq / 32; kt++) {
        const int kbase = kt * 32;
        __syncthreads();   // protect Kts/Vs/Pts from previous iteration's readers

        // Load K tile (transposed) and V tile (natural); coalesced gmem
#pragma unroll
        for (int i = 0; i < 8; i++) {
            int e = i * 256 + tid;
            int r = e >> 6, d = e & 63;
            size_t g = ((size_t)b * Sq + kbase + r) * DOq + d;
            Kts[d][r] = gk[g];
            Vs[r][d]  = gv[g];
        }
        // Mask for this thread's 4x2 score patch (int2 = 2 consecutive cols)
        int2 mk[4];
#pragma unroll
        for (int r = 0; r < 4; r++)
            mk[r] = *(const int2*)(mrow[r] + kbase);
        __syncthreads();

        // ---- S = Q @ K^T (packed over row pairs) ----
        ull s2[2][2] = {{0ull, 0ull}, {0ull, 0ull}};
#pragma unroll
        for (int d = 0; d < 64; d++) {
            ulonglong2 a = *(const ulonglong2*)&Qts[d][4 * ty];
            ull k0d = dup2(Kts[d][2 * tx]);
            ull k1d = dup2(Kts[d][2 * tx + 1]);
            s2[0][0] = fma2(a.x, k0d, s2[0][0]);
            s2[0][1] = fma2(a.x, k1d, s2[0][1]);
            s2[1][0] = fma2(a.y, k0d, s2[1][0]);
            s2[1][1] = fma2(a.y, k1d, s2[1][1]);
        }

        // Unpack, scale by 1/sqrt(64), apply mask
        float sc[4][2];
#pragma unroll
        for (int rr = 0; rr < 2; rr++)
#pragma unroll
            for (int cc = 0; cc < 2; cc++) {
                float2 v = unpack2(s2[rr][cc]);
                sc[2 * rr][cc]     = v.x * 0.125f;
                sc[2 * rr + 1][cc] = v.y * 0.125f;
            }
#pragma unroll
        for (int r = 0; r < 4; r++) {
            if (mk[r].x == 0) sc[r][0] = NEGINF;
            if (mk[r].y == 0) sc[r][1] = NEGINF;
        }

        // ---- online softmax ----
        float rm[4];
#pragma unroll
        for (int r = 0; r < 4; r++)
            rm[r] = fmaxf(sc[r][0], sc[r][1]);
        // all-reduce max across the 16 tx lanes of this row group
#pragma unroll
        for (int off = 1; off < 16; off <<= 1)
#pragma unroll
            for (int r = 0; r < 4; r++)
                rm[r] = fmaxf(rm[r], __shfl_xor_sync(0xffffffffu, rm[r], off));

        float p[4][2], corr[4], rs[4];
#pragma unroll
        for (int r = 0; r < 4; r++) {
            float mn = fmaxf(m_i[r], rm[r]);
            if (mn == NEGINF) {            // fully-masked-so-far row: avoid NaN
                corr[r] = 1.0f; p[r][0] = 0.0f; p[r][1] = 0.0f;
            } else {
                corr[r] = __expf(m_i[r] - mn);       // m_i = -inf -> 0
                p[r][0] = __expf(sc[r][0] - mn);      // sc = -inf -> 0
                p[r][1] = __expf(sc[r][1] - mn);
            }
            m_i[r] = mn;
            rs[r] = p[r][0] + p[r][1];
        }
#pragma unroll
        for (int off = 1; off < 16; off <<= 1)
#pragma unroll
            for (int r = 0; r < 4; r++)
                rs[r] += __shfl_xor_sync(0xffffffffu, rs[r], off);
#pragma unroll
        for (int r = 0; r < 4; r++)
            l_i[r] = l_i[r] * corr[r] + rs[r];

        // Rescale O accumulators (packed row-pair correction)
        ull c2[2] = { pack2(corr[0], corr[1]), pack2(corr[2], corr[3]) };
#pragma unroll
        for (int rr = 0; rr < 2; rr++)
#pragma unroll
            for (int c = 0; c < 4; c++)
                O2[rr][c] = mul2(O2[rr][c], c2[rr]);

        // Stage P transposed: Pts[col][4ty..4ty+3] as one float4 per col
        *(float4*)&Pts[2 * tx][4 * ty] =
            make_float4(p[0][0], p[1][0], p[2][0], p[3][0]);
        *(float4*)&Pts[2 * tx + 1][4 * ty] =
            make_float4(p[0][1], p[1][1], p[2][1], p[3][1]);
        __syncthreads();

        // ---- O += P @ V (packed over row pairs; P pairs straight from SMEM) ----
#pragma unroll
        for (int k = 0; k < 32; k++) {
            ulonglong2 a = *(const ulonglong2*)&Pts[k][4 * ty];
            float4 v = *(const float4*)&Vs[k][4 * tx];
            ull v0 = dup2(v.x), v1 = dup2(v.y), v2 = dup2(v.z), v3 = dup2(v.w);
            O2[0][0] = fma2(a.x, v0, O2[0][0]);
            O2[0][1] = fma2(a.x, v1, O2[0][1]);
            O2[0][2] = fma2(a.x, v2, O2[0][2]);
            O2[0][3] = fma2(a.x, v3, O2[0][3]);
            O2[1][0] = fma2(a.y, v0, O2[1][0]);
            O2[1][1] = fma2(a.y, v1, O2[1][1]);
            O2[1][2] = fma2(a.y, v2, O2[1][2]);
            O2[1][3] = fma2(a.y, v3, O2[1][3]);
        }
    }

    // Normalize and write
    float inv[4];
#pragma unroll
    for (int r = 0; r < 4; r++)
        inv[r] = (l_i[r] > 0.0f) ? (1.0f / l_i[r]) : 0.0f;

#pragma unroll
    for (int rr = 0; rr < 2; rr++) {
        float o0[4], o1[4];
#pragma unroll
        for (int c = 0; c < 4; c++) {
            float2 v = unpack2(O2[rr][c]);
            o0[c] = v.x * inv[2 * rr];
            o1[c] = v.y * inv[2 * rr + 1];
        }
        size_t orow = ((size_t)b * Sq + q0 + 4 * ty + 2 * rr) * DOq + 4 * tx;
        *(float4*)&out[orow]       = make_float4(o0[0], o0[1], o0[2], o0[3]);
        *(float4*)&out[orow + DOq] = make_float4(o1[0], o1[1], o1[2], o1[3]);
    }
}

// ---------------------------------------------------------------------------
// Launch
// ---------------------------------------------------------------------------
extern "C" void kernel_launch(void* const* d_in, const int* in_sizes, int n_in,
                              void* d_out, int out_size)
{
    const float* query = (const float*)d_in[0];
    const float* key_t = (const float*)d_in[1];
    const float* value = (const float*)d_in[2];
    const int*   mask  = (const int*)  d_in[3];
    const float* Wq    = (const float*)d_in[4];
    const float* bq    = (const float*)d_in[5];
    const float* Wk    = (const float*)d_in[6];
    const float* bk    = (const float*)d_in[7];
    const float* Wv    = (const float*)d_in[8];
    const float* bv    = (const float*)d_in[9];
    float* out = (float*)d_out;

    dim3 pblk(256), pgrd((Bq * Sq) / 64);
    proj_kernel<<<pgrd, pblk>>>(query, Wq, bq, 0);
    proj_kernel<<<pgrd, pblk>>>(key_t, Wk, bk, 1);
    proj_kernel<<<pgrd, pblk>>>(value, Wv, bv, 2);

    dim3 ablk(256), agrd(Sq / 64, Bq);
    attn_kernel<<<agrd, ablk>>>(mask, out);
}